// round 2
// baseline (speedup 1.0000x reference)
#include <cuda_runtime.h>
#include <stdint.h>

#define BB 2
#define TT 2048
#define CC 1024
#define HH 16
#define DD 64

// Scratch (allocation-free rule: __device__ globals)
__device__ float g_q[BB * HH * TT * DD];
__device__ float g_k[BB * HH * TT * DD];
__device__ float g_v[BB * HH * TT * DD];
__device__ float g_ao[BB * TT * CC];

// ---------------------------------------------------------------------------
// Threefry-2x32, key = (0, 42)  (== jax.random.key(42))
// ---------------------------------------------------------------------------
__device__ __forceinline__ uint2 threefry_0_42(uint32_t x0, uint32_t x1) {
    const uint32_t ks0 = 0u;
    const uint32_t ks1 = 42u;
    const uint32_t ks2 = 0x1BD11BDAu ^ ks0 ^ ks1;
    x0 += ks0; x1 += ks1;
#define TF_RND(rot) { x0 += x1; x1 = __funnelshift_l(x1, x1, (rot)); x1 ^= x0; }
    TF_RND(13) TF_RND(15) TF_RND(26) TF_RND(6)
    x0 += ks1; x1 += ks2 + 1u;
    TF_RND(17) TF_RND(29) TF_RND(16) TF_RND(24)
    x0 += ks2; x1 += ks0 + 2u;
    TF_RND(13) TF_RND(15) TF_RND(26) TF_RND(6)
    x0 += ks0; x1 += ks1 + 3u;
    TF_RND(17) TF_RND(29) TF_RND(16) TF_RND(24)
    x0 += ks1; x1 += ks2 + 4u;
    TF_RND(13) TF_RND(15) TF_RND(26) TF_RND(6)
    x0 += ks2; x1 += ks0 + 5u;
#undef TF_RND
    return make_uint2(x0, x1);
}

// Partitionable-mode regrow test: element with 64-bit flat index (hi=0, lo=idx):
//   bits = lane0 ^ lane1 of threefry((0,42), (0, idx));  u = (bits>>9)*2^-23
//   regrow  <=>  u < 0.05f  <=>  (bits>>9) <= 419430
__device__ __forceinline__ bool regrow_test(uint32_t idx) {
    uint2 rb = threefry_0_42(0u, idx);
    uint32_t bits = rb.x ^ rb.y;
    return (bits >> 9) <= 419430u;
}

// ---------------------------------------------------------------------------
// GEMM: C[M,N] = A[M,K] @ B[K,N] + bias[N]
// mode 0: plain row-major store into Cout (A taken from g_ao)
// mode 1: scatter into g_q/g_k/g_v in [B,H,T,D] layout (A = x)
// BM=BN=128, BK=16, 256 threads, 8x8 per thread.
// ---------------------------------------------------------------------------
__global__ void __launch_bounds__(256)
gemm_kernel(const float* __restrict__ A_in, const float* __restrict__ Bmat,
            const float* __restrict__ bias, float* __restrict__ Cout,
            int M, int N, int K, int mode) {
    __shared__ float As[16][132];
    __shared__ float Bs[16][132];

    const float* A = (mode == 1) ? A_in : (const float*)g_ao;

    int tid = threadIdx.x;
    int tx = tid & 15, ty = tid >> 4;
    int m0 = blockIdx.y * 128, n0 = blockIdx.x * 128;

    float acc[8][8];
#pragma unroll
    for (int i = 0; i < 8; i++)
#pragma unroll
        for (int j = 0; j < 8; j++) acc[i][j] = 0.f;

    for (int k0 = 0; k0 < K; k0 += 16) {
        // Load A tile (128x16), store transposed As[k][m]
#pragma unroll
        for (int rep = 0; rep < 2; rep++) {
            int e = tid + rep * 256;
            int r = e >> 2, c4 = e & 3;
            float4 av = *(const float4*)&A[(size_t)(m0 + r) * K + k0 + c4 * 4];
            As[c4 * 4 + 0][r] = av.x;
            As[c4 * 4 + 1][r] = av.y;
            As[c4 * 4 + 2][r] = av.z;
            As[c4 * 4 + 3][r] = av.w;
        }
        // Load B tile (16x128)
#pragma unroll
        for (int rep = 0; rep < 2; rep++) {
            int e = tid + rep * 256;
            int r = e >> 5, c4 = e & 31;
            float4 bv = *(const float4*)&Bmat[(size_t)(k0 + r) * N + n0 + c4 * 4];
            *(float4*)&Bs[r][c4 * 4] = bv;
        }
        __syncthreads();

#pragma unroll
        for (int kk = 0; kk < 16; kk++) {
            float a[8], b[8];
            *(float4*)&a[0] = *(const float4*)&As[kk][ty * 4];
            *(float4*)&a[4] = *(const float4*)&As[kk][64 + ty * 4];
            *(float4*)&b[0] = *(const float4*)&Bs[kk][tx * 4];
            *(float4*)&b[4] = *(const float4*)&Bs[kk][64 + tx * 4];
#pragma unroll
            for (int i = 0; i < 8; i++)
#pragma unroll
                for (int j = 0; j < 8; j++) acc[i][j] += a[i] * b[j];
        }
        __syncthreads();
    }

    // Epilogue: bias add, then store / scatter
#pragma unroll
    for (int i = 0; i < 8; i++) {
        int m = m0 + ((i < 4) ? (ty * 4 + i) : (64 + ty * 4 + (i - 4)));
#pragma unroll
        for (int jg = 0; jg < 2; jg++) {
            int n = n0 + tx * 4 + jg * 64;
            float4 val;
            val.x = acc[i][jg * 4 + 0] + bias[n + 0];
            val.y = acc[i][jg * 4 + 1] + bias[n + 1];
            val.z = acc[i][jg * 4 + 2] + bias[n + 2];
            val.w = acc[i][jg * 4 + 3] + bias[n + 3];
            if (mode == 0) {
                *(float4*)&Cout[(size_t)m * N + n] = val;
            } else {
                int part = n >> 10;
                int rem = n & 1023;
                int h = rem >> 6;
                int d = rem & 63;
                int b = m >> 11;
                int t = m & 2047;
                float* dst = (part == 0) ? g_q : (part == 1) ? g_k : g_v;
                *(float4*)&dst[((((size_t)b * HH) + h) * TT + t) * DD + d] = val;
            }
        }
    }
}

// ---------------------------------------------------------------------------
// Two-pass causal attention with neuroplastic sparsification.
// Block: 32 query rows of one (b,h); 256 threads = 32 rows x 8 lanes.
// Pass 1: streaming online max/sumexp over 32-wide key tiles.
// Pass 2: recompute scores, p = exp(s-m)/l, keep = p>0.01 || regrow,
//         accumulate (p*keep) @ V.
// ---------------------------------------------------------------------------
__global__ void __launch_bounds__(256)
attn_kernel() {
    __shared__ float q_sm[32][64];
    __shared__ float k_sm[32][68];
    __shared__ float v_sm[32][68];
    __shared__ float a_sm[32][33];

    const int b = blockIdx.z;
    const int h = blockIdx.y;
    const int qb = blockIdx.x;
    const int t0 = qb * 32;
    const int tid = threadIdx.x;
    const int r = tid >> 3;
    const int lane8 = tid & 7;

    const float* qbase = g_q + ((size_t)(b * HH + h) * TT) * DD;
    const float* kbase = g_k + ((size_t)(b * HH + h) * TT) * DD;
    const float* vbase = g_v + ((size_t)(b * HH + h) * TT) * DD;

    // Load Q tile
#pragma unroll
    for (int rep = 0; rep < 2; rep++) {
        int e = tid + rep * 256;
        int rr = e >> 4, d4 = e & 15;
        *(float4*)&q_sm[rr][d4 * 4] =
            *(const float4*)&qbase[(size_t)(t0 + rr) * 64 + d4 * 4];
    }

    const int t = t0 + r;
    const int ntiles = qb + 1;

    float m = -1e30f, l = 0.f;

    // ---------------- Pass 1: row max + sumexp ----------------
    for (int it = 0; it < ntiles; it++) {
        int s0 = it * 32;
        __syncthreads();
#pragma unroll
        for (int rep = 0; rep < 2; rep++) {
            int e = tid + rep * 256;
            int rr = e >> 4, d4 = e & 15;
            *(float4*)&k_sm[rr][d4 * 4] =
                *(const float4*)&kbase[(size_t)(s0 + rr) * 64 + d4 * 4];
        }
        __syncthreads();

        float sc[4] = {0.f, 0.f, 0.f, 0.f};
#pragma unroll
        for (int d4 = 0; d4 < 16; d4++) {
            float4 qv = *(const float4*)&q_sm[r][d4 * 4];
#pragma unroll
            for (int j = 0; j < 4; j++) {
                float4 kv = *(const float4*)&k_sm[lane8 + 8 * j][d4 * 4];
                sc[j] += qv.x * kv.x + qv.y * kv.y + qv.z * kv.z + qv.w * kv.w;
            }
        }
        float tm = -1e30f;
#pragma unroll
        for (int j = 0; j < 4; j++) {
            int s = s0 + lane8 + 8 * j;
            sc[j] = (s <= t) ? sc[j] * 0.125f : -1e30f;
            tm = fmaxf(tm, sc[j]);
        }
#pragma unroll
        for (int off = 4; off > 0; off >>= 1)
            tm = fmaxf(tm, __shfl_xor_sync(0xffffffffu, tm, off));
        float mn = fmaxf(m, tm);
        float ls = 0.f;
#pragma unroll
        for (int j = 0; j < 4; j++) ls += __expf(sc[j] - mn);
#pragma unroll
        for (int off = 4; off > 0; off >>= 1)
            ls += __shfl_xor_sync(0xffffffffu, ls, off);
        l = l * __expf(m - mn) + ls;
        m = mn;
    }

    const float inv_l = 1.0f / l;
    // 64-bit flat index of (b,h,t,0) in [B,H,T,T]; fits in uint32 (2^27 max).
    const uint32_t idx_base =
        ((uint32_t)((b * HH + h) * TT + t)) * (uint32_t)TT;
    float oacc[8] = {0.f, 0.f, 0.f, 0.f, 0.f, 0.f, 0.f, 0.f};

    // ---------------- Pass 2: sparsified A @ V ----------------
    for (int it = 0; it < ntiles; it++) {
        int s0 = it * 32;
        __syncthreads();
#pragma unroll
        for (int rep = 0; rep < 2; rep++) {
            int e = tid + rep * 256;
            int rr = e >> 4, d4 = e & 15;
            *(float4*)&k_sm[rr][d4 * 4] =
                *(const float4*)&kbase[(size_t)(s0 + rr) * 64 + d4 * 4];
            *(float4*)&v_sm[rr][d4 * 4] =
                *(const float4*)&vbase[(size_t)(s0 + rr) * 64 + d4 * 4];
        }
        __syncthreads();

        float sc[4] = {0.f, 0.f, 0.f, 0.f};
#pragma unroll
        for (int d4 = 0; d4 < 16; d4++) {
            float4 qv = *(const float4*)&q_sm[r][d4 * 4];
#pragma unroll
            for (int j = 0; j < 4; j++) {
                float4 kv = *(const float4*)&k_sm[lane8 + 8 * j][d4 * 4];
                sc[j] += qv.x * kv.x + qv.y * kv.y + qv.z * kv.z + qv.w * kv.w;
            }
        }
#pragma unroll
        for (int j = 0; j < 4; j++) {
            int s = s0 + lane8 + 8 * j;
            float sval = (s <= t) ? sc[j] * 0.125f : -1e30f;
            float p = __expf(sval - m) * inv_l;
            bool keep = (p > 0.01f) || regrow_test(idx_base + (uint32_t)s);
            a_sm[r][lane8 + 8 * j] = keep ? p : 0.0f;
        }
        __syncthreads();

#pragma unroll
        for (int ts = 0; ts < 32; ts++) {
            float av = a_sm[r][ts];
            float4 v0 = *(const float4*)&v_sm[ts][lane8 * 8];
            float4 v1 = *(const float4*)&v_sm[ts][lane8 * 8 + 4];
            oacc[0] += av * v0.x; oacc[1] += av * v0.y;
            oacc[2] += av * v0.z; oacc[3] += av * v0.w;
            oacc[4] += av * v1.x; oacc[5] += av * v1.y;
            oacc[6] += av * v1.z; oacc[7] += av * v1.w;
        }
    }

    // Store to [B, T, C] with c = h*64 + d
    float* dst = g_ao + ((size_t)(b * TT + t) * CC) + h * 64 + lane8 * 8;
    *(float4*)&dst[0] = make_float4(oacc[0], oacc[1], oacc[2], oacc[3]);
    *(float4*)&dst[4] = make_float4(oacc[4], oacc[5], oacc[6], oacc[7]);
}

// ---------------------------------------------------------------------------
extern "C" void kernel_launch(void* const* d_in, const int* in_sizes, int n_in,
                              void* d_out, int out_size) {
    const float* x    = (const float*)d_in[0];
    const float* Wqkv = (const float*)d_in[1];
    const float* bqkv = (const float*)d_in[2];
    const float* Wout = (const float*)d_in[3];
    const float* bout = (const float*)d_in[4];
    float* out = (float*)d_out;

    // 1) QKV projection, scattered to [B,H,T,D]
    gemm_kernel<<<dim3(3 * CC / 128, BB * TT / 128), 256>>>(
        x, Wqkv, bqkv, nullptr, BB * TT, 3 * CC, CC, 1);

    // 2) Causal attention + neuroplastic sparsification
    attn_kernel<<<dim3(TT / 32, HH, BB), 256>>>();

    // 3) Output projection
    gemm_kernel<<<dim3(CC / 128, BB * TT / 128), 256>>>(
        nullptr, Wout, bout, out, BB * TT, CC, CC, 0);
}

// round 3
// speedup vs baseline: 1.2523x; 1.2523x over previous
#include <cuda_runtime.h>
#include <stdint.h>

#define BB 2
#define TT 2048
#define CC 1024
#define HH 16
#define DD 64

// Scratch (allocation-free rule: __device__ globals)
__device__ float g_q[BB * HH * TT * DD];
__device__ float g_k[BB * HH * TT * DD];
__device__ float g_v[BB * HH * TT * DD];
__device__ float g_ao[BB * TT * CC];
// Cached unnormalized softmax numerators e = exp(s - m_running), per (b,h,t,s)
__device__ float g_e[(size_t)BB * HH * TT * TT];

// ---------------------------------------------------------------------------
// Threefry-2x32, key = (0, 42)  (== jax.random.key(42))
// ---------------------------------------------------------------------------
__device__ __forceinline__ uint2 threefry_0_42(uint32_t x0, uint32_t x1) {
    const uint32_t ks0 = 0u;
    const uint32_t ks1 = 42u;
    const uint32_t ks2 = 0x1BD11BDAu ^ ks0 ^ ks1;
    x0 += ks0; x1 += ks1;
#define TF_RND(rot) { x0 += x1; x1 = __funnelshift_l(x1, x1, (rot)); x1 ^= x0; }
    TF_RND(13) TF_RND(15) TF_RND(26) TF_RND(6)
    x0 += ks1; x1 += ks2 + 1u;
    TF_RND(17) TF_RND(29) TF_RND(16) TF_RND(24)
    x0 += ks2; x1 += ks0 + 2u;
    TF_RND(13) TF_RND(15) TF_RND(26) TF_RND(6)
    x0 += ks0; x1 += ks1 + 3u;
    TF_RND(17) TF_RND(29) TF_RND(16) TF_RND(24)
    x0 += ks1; x1 += ks2 + 4u;
    TF_RND(13) TF_RND(15) TF_RND(26) TF_RND(6)
    x0 += ks2; x1 += ks0 + 5u;
#undef TF_RND
    return make_uint2(x0, x1);
}

// Partitionable-mode regrow: bits = lane0 ^ lane1 of threefry((0,42),(0,idx));
// u = (bits>>9)*2^-23 ; regrow <=> u < 0.05f <=> (bits>>9) <= 419430
__device__ __forceinline__ bool regrow_test(uint32_t idx) {
    uint2 rb = threefry_0_42(0u, idx);
    uint32_t bits = rb.x ^ rb.y;
    return (bits >> 9) <= 419430u;
}

// ---------------------------------------------------------------------------
// GEMM: C[M,N] = A[M,K] @ B[K,N] + bias[N]
// mode 0: plain row-major store into Cout (A taken from g_ao)
// mode 1: scatter into g_q/g_k/g_v in [B,H,T,D] layout (A = x)
// BM=BN=128, BK=16, 256 threads, 8x8 per thread.
// ---------------------------------------------------------------------------
__global__ void __launch_bounds__(256)
gemm_kernel(const float* __restrict__ A_in, const float* __restrict__ Bmat,
            const float* __restrict__ bias, float* __restrict__ Cout,
            int M, int N, int K, int mode) {
    __shared__ float As[16][132];
    __shared__ float Bs[16][132];

    const float* A = (mode == 1) ? A_in : (const float*)g_ao;

    int tid = threadIdx.x;
    int tx = tid & 15, ty = tid >> 4;
    int m0 = blockIdx.y * 128, n0 = blockIdx.x * 128;

    float acc[8][8];
#pragma unroll
    for (int i = 0; i < 8; i++)
#pragma unroll
        for (int j = 0; j < 8; j++) acc[i][j] = 0.f;

    for (int k0 = 0; k0 < K; k0 += 16) {
#pragma unroll
        for (int rep = 0; rep < 2; rep++) {
            int e = tid + rep * 256;
            int r = e >> 2, c4 = e & 3;
            float4 av = *(const float4*)&A[(size_t)(m0 + r) * K + k0 + c4 * 4];
            As[c4 * 4 + 0][r] = av.x;
            As[c4 * 4 + 1][r] = av.y;
            As[c4 * 4 + 2][r] = av.z;
            As[c4 * 4 + 3][r] = av.w;
        }
#pragma unroll
        for (int rep = 0; rep < 2; rep++) {
            int e = tid + rep * 256;
            int r = e >> 5, c4 = e & 31;
            float4 bv = *(const float4*)&Bmat[(size_t)(k0 + r) * N + n0 + c4 * 4];
            *(float4*)&Bs[r][c4 * 4] = bv;
        }
        __syncthreads();

#pragma unroll
        for (int kk = 0; kk < 16; kk++) {
            float a[8], b[8];
            *(float4*)&a[0] = *(const float4*)&As[kk][ty * 4];
            *(float4*)&a[4] = *(const float4*)&As[kk][64 + ty * 4];
            *(float4*)&b[0] = *(const float4*)&Bs[kk][tx * 4];
            *(float4*)&b[4] = *(const float4*)&Bs[kk][64 + tx * 4];
#pragma unroll
            for (int i = 0; i < 8; i++)
#pragma unroll
                for (int j = 0; j < 8; j++) acc[i][j] += a[i] * b[j];
        }
        __syncthreads();
    }

#pragma unroll
    for (int i = 0; i < 8; i++) {
        int m = m0 + ((i < 4) ? (ty * 4 + i) : (64 + ty * 4 + (i - 4)));
#pragma unroll
        for (int jg = 0; jg < 2; jg++) {
            int n = n0 + tx * 4 + jg * 64;
            float4 val;
            val.x = acc[i][jg * 4 + 0] + bias[n + 0];
            val.y = acc[i][jg * 4 + 1] + bias[n + 1];
            val.z = acc[i][jg * 4 + 2] + bias[n + 2];
            val.w = acc[i][jg * 4 + 3] + bias[n + 3];
            if (mode == 0) {
                *(float4*)&Cout[(size_t)m * N + n] = val;
            } else {
                int part = n >> 10;
                int rem = n & 1023;
                int h = rem >> 6;
                int d = rem & 63;
                int b = m >> 11;
                int t = m & 2047;
                float* dst = (part == 0) ? g_q : (part == 1) ? g_k : g_v;
                *(float4*)&dst[((((size_t)b * HH) + h) * TT + t) * DD + d] = val;
            }
        }
    }
}

// ---------------------------------------------------------------------------
// Two-pass causal attention with neuroplastic sparsification, with cached
// exponentials: pass 1 computes QK once, stores e = exp(s - m_running) to
// gmem scratch and the per-(row,tile) running max; pass 2 rescales cached e
// by c_it = exp(m_it - m_final)/l, applies threshold||regrow, accumulates AV.
// Block: 32 query rows of one (b,h); 256 threads = 32 rows x 8 lanes.
// ---------------------------------------------------------------------------
__global__ void __launch_bounds__(256)
attn_kernel() {
    __shared__ float q_sm[32][68];
    __shared__ float kv_sm[32][68];
    __shared__ float a_sm[32][33];
    __shared__ float mh[32][64];      // running max per (row, tile) -> factor

    const int b = blockIdx.z;
    const int h = blockIdx.y;
    const int qb = blockIdx.x;
    const int t0 = qb * 32;
    const int tid = threadIdx.x;
    const int r = tid >> 3;
    const int lane8 = tid & 7;

    const float* qbase = g_q + ((size_t)(b * HH + h) * TT) * DD;
    const float* kbase = g_k + ((size_t)(b * HH + h) * TT) * DD;
    const float* vbase = g_v + ((size_t)(b * HH + h) * TT) * DD;

    const int t = t0 + r;
    float* erow = g_e + ((size_t)((b * HH + h) * TT + t)) * TT;

    // Load Q tile
#pragma unroll
    for (int rep = 0; rep < 2; rep++) {
        int e = tid + rep * 256;
        int rr = e >> 4, d4 = e & 15;
        *(float4*)&q_sm[rr][d4 * 4] =
            *(const float4*)&qbase[(size_t)(t0 + rr) * 64 + d4 * 4];
    }

    const int ntiles = qb + 1;
    float m = -1e30f, l = 0.f;

    // ---------------- Pass 1: QK once, online max/sum, cache e ----------------
    for (int it = 0; it < ntiles; it++) {
        int s0 = it * 32;
        __syncthreads();
#pragma unroll
        for (int rep = 0; rep < 2; rep++) {
            int e = tid + rep * 256;
            int rr = e >> 4, d4 = e & 15;
            *(float4*)&kv_sm[rr][d4 * 4] =
                *(const float4*)&kbase[(size_t)(s0 + rr) * 64 + d4 * 4];
        }
        __syncthreads();

        float sc[4] = {0.f, 0.f, 0.f, 0.f};
#pragma unroll
        for (int d4 = 0; d4 < 16; d4++) {
            float4 qv = *(const float4*)&q_sm[r][d4 * 4];
#pragma unroll
            for (int j = 0; j < 4; j++) {
                float4 kv = *(const float4*)&kv_sm[lane8 + 8 * j][d4 * 4];
                sc[j] += qv.x * kv.x + qv.y * kv.y + qv.z * kv.z + qv.w * kv.w;
            }
        }
        float tm = -1e30f;
#pragma unroll
        for (int j = 0; j < 4; j++) {
            int s = s0 + lane8 + 8 * j;
            sc[j] = (s <= t) ? sc[j] * 0.125f : -1e30f;
            tm = fmaxf(tm, sc[j]);
        }
#pragma unroll
        for (int off = 4; off > 0; off >>= 1)
            tm = fmaxf(tm, __shfl_xor_sync(0xffffffffu, tm, off));
        float mn = fmaxf(m, tm);
        float ev[4], ls = 0.f;
#pragma unroll
        for (int j = 0; j < 4; j++) {
            ev[j] = __expf(sc[j] - mn);   // <= 1, ==0 for masked
            ls += ev[j];
        }
#pragma unroll
        for (int off = 4; off > 0; off >>= 1)
            ls += __shfl_xor_sync(0xffffffffu, ls, off);
        l = l * __expf(m - mn) + ls;
        m = mn;
        if (lane8 == 0) mh[r][it] = mn;
        // store cached numerators (4x STG.32, 32B-chunk coalesced per row)
#pragma unroll
        for (int j = 0; j < 4; j++)
            erow[s0 + lane8 + 8 * j] = ev[j];
    }

    // Per-tile rescale factors: c_it = exp(m_it - m_final) / l
    __syncthreads();
    {
        const float inv_l = 1.0f / l;
        for (int it = lane8; it < ntiles; it += 8)
            mh[r][it] = __expf(mh[r][it] - m) * inv_l;
    }

    const uint32_t idx_base =
        ((uint32_t)((b * HH + h) * TT + t)) * (uint32_t)TT;
    float oacc[8] = {0.f, 0.f, 0.f, 0.f, 0.f, 0.f, 0.f, 0.f};

    // ---------------- Pass 2: sparsify cached e, A @ V ----------------
    for (int it = 0; it < ntiles; it++) {
        int s0 = it * 32;
        __syncthreads();
#pragma unroll
        for (int rep = 0; rep < 2; rep++) {
            int e = tid + rep * 256;
            int rr = e >> 4, d4 = e & 15;
            *(float4*)&kv_sm[rr][d4 * 4] =
                *(const float4*)&vbase[(size_t)(s0 + rr) * 64 + d4 * 4];
        }
        const float fac = mh[r][it];
        float4 evec = *(const float4*)&erow[s0 + lane8 * 4];
        float ee[4] = {evec.x, evec.y, evec.z, evec.w};
#pragma unroll
        for (int j = 0; j < 4; j++) {
            int s = s0 + lane8 * 4 + j;
            float p = ee[j] * fac;
            bool keep = (p > 0.01f) || regrow_test(idx_base + (uint32_t)s);
            a_sm[r][lane8 * 4 + j] = keep ? p : 0.0f;
        }
        __syncthreads();

#pragma unroll
        for (int ts = 0; ts < 32; ts++) {
            float av = a_sm[r][ts];
            float4 v0 = *(const float4*)&kv_sm[ts][lane8 * 8];
            float4 v1 = *(const float4*)&kv_sm[ts][lane8 * 8 + 4];
            oacc[0] += av * v0.x; oacc[1] += av * v0.y;
            oacc[2] += av * v0.z; oacc[3] += av * v0.w;
            oacc[4] += av * v1.x; oacc[5] += av * v1.y;
            oacc[6] += av * v1.z; oacc[7] += av * v1.w;
        }
    }

    // Store to [B, T, C] with c = h*64 + d
    float* dst = g_ao + ((size_t)(b * TT + t) * CC) + h * 64 + lane8 * 8;
    *(float4*)&dst[0] = make_float4(oacc[0], oacc[1], oacc[2], oacc[3]);
    *(float4*)&dst[4] = make_float4(oacc[4], oacc[5], oacc[6], oacc[7]);
}

// ---------------------------------------------------------------------------
extern "C" void kernel_launch(void* const* d_in, const int* in_sizes, int n_in,
                              void* d_out, int out_size) {
    const float* x    = (const float*)d_in[0];
    const float* Wqkv = (const float*)d_in[1];
    const float* bqkv = (const float*)d_in[2];
    const float* Wout = (const float*)d_in[3];
    const float* bout = (const float*)d_in[4];
    float* out = (float*)d_out;

    // 1) QKV projection, scattered to [B,H,T,D]
    gemm_kernel<<<dim3(3 * CC / 128, BB * TT / 128), 256>>>(
        x, Wqkv, bqkv, nullptr, BB * TT, 3 * CC, CC, 1);

    // 2) Causal attention + neuroplastic sparsification
    attn_kernel<<<dim3(TT / 32, HH, BB), 256>>>();

    // 3) Output projection
    gemm_kernel<<<dim3(CC / 128, BB * TT / 128), 256>>>(
        nullptr, Wout, bout, out, BB * TT, CC, CC, 0);
}

// round 4
// speedup vs baseline: 1.6117x; 1.2870x over previous
#include <cuda_runtime.h>
#include <stdint.h>

#define BB 2
#define TT 2048
#define CC 1024
#define HH 16
#define DD 64

// Scratch (allocation-free rule: __device__ globals)
__device__ float g_q[BB * HH * TT * DD];
__device__ float g_k[BB * HH * TT * DD];
__device__ float g_v[BB * HH * TT * DD];
__device__ float g_ao[BB * TT * CC];
// Cached unnormalized softmax numerators e = exp(s - m_running), per (b,h,t,s)
__device__ float g_e[(size_t)BB * HH * TT * TT];
// Regrow bitmask: 64 words of 32 bits per (bh, t) row
__device__ uint32_t g_mask[(size_t)BB * HH * TT * (TT / 32)];

// ---------------------------------------------------------------------------
// Threefry-2x32, key = (0, 42)  (== jax.random.key(42))
// ---------------------------------------------------------------------------
__device__ __forceinline__ uint2 threefry_0_42(uint32_t x0, uint32_t x1) {
    const uint32_t ks0 = 0u;
    const uint32_t ks1 = 42u;
    const uint32_t ks2 = 0x1BD11BDAu ^ ks0 ^ ks1;
    x0 += ks0; x1 += ks1;
#define TF_RND(rot) { x0 += x1; x1 = __funnelshift_l(x1, x1, (rot)); x1 ^= x0; }
    TF_RND(13) TF_RND(15) TF_RND(26) TF_RND(6)
    x0 += ks1; x1 += ks2 + 1u;
    TF_RND(17) TF_RND(29) TF_RND(16) TF_RND(24)
    x0 += ks2; x1 += ks0 + 2u;
    TF_RND(13) TF_RND(15) TF_RND(26) TF_RND(6)
    x0 += ks0; x1 += ks1 + 3u;
    TF_RND(17) TF_RND(29) TF_RND(16) TF_RND(24)
    x0 += ks1; x1 += ks2 + 4u;
    TF_RND(13) TF_RND(15) TF_RND(26) TF_RND(6)
    x0 += ks2; x1 += ks0 + 5u;
#undef TF_RND
    return make_uint2(x0, x1);
}

// Partitionable-mode regrow: bits = lane0 ^ lane1 of threefry((0,42),(0,idx));
// u = (bits>>9)*2^-23 ; regrow <=> u < 0.05f <=> (bits>>9) <= 419430
__device__ __forceinline__ bool regrow_test(uint32_t idx) {
    uint2 rb = threefry_0_42(0u, idx);
    uint32_t bits = rb.x ^ rb.y;
    return (bits >> 9) <= 419430u;
}

// ---------------------------------------------------------------------------
// Regrow mask precompute: pure function of (bh, t, s). One warp per 32-bit
// word; ballot assembles the word. Upper-triangle words skipped.
// grid (8, TT, BB*HH), block 256 (8 warps).
// ---------------------------------------------------------------------------
__global__ void __launch_bounds__(256)
mask_kernel() {
    const int t  = blockIdx.y;
    const int bh = blockIdx.z;
    const int w  = blockIdx.x * 8 + (threadIdx.x >> 5);
    if (w * 32 > t) return;              // word entirely in masked region
    const int lane = threadIdx.x & 31;
    const uint32_t s = (uint32_t)(w * 32 + lane);
    const uint32_t idx = ((uint32_t)(bh * TT + t)) * (uint32_t)TT + s;
    uint32_t word = __ballot_sync(0xffffffffu, regrow_test(idx));
    if (lane == 0) g_mask[((size_t)(bh * TT + t)) * (TT / 32) + w] = word;
}

// ---------------------------------------------------------------------------
// GEMM: C[M,N] = A[M,K] @ B[K,N] + bias[N]
// mode 0: plain row-major store into Cout (A taken from g_ao)
// mode 1: scatter into g_q/g_k/g_v in [B,H,T,D] layout (A = x)
// BM=BN=128, BK=16, 256 threads, 8x8 per thread.
// ---------------------------------------------------------------------------
__global__ void __launch_bounds__(256)
gemm_kernel(const float* __restrict__ A_in, const float* __restrict__ Bmat,
            const float* __restrict__ bias, float* __restrict__ Cout,
            int M, int N, int K, int mode) {
    __shared__ float As[16][132];
    __shared__ float Bs[16][132];

    const float* A = (mode == 1) ? A_in : (const float*)g_ao;

    int tid = threadIdx.x;
    int tx = tid & 15, ty = tid >> 4;
    int m0 = blockIdx.y * 128, n0 = blockIdx.x * 128;

    float acc[8][8];
#pragma unroll
    for (int i = 0; i < 8; i++)
#pragma unroll
        for (int j = 0; j < 8; j++) acc[i][j] = 0.f;

    for (int k0 = 0; k0 < K; k0 += 16) {
#pragma unroll
        for (int rep = 0; rep < 2; rep++) {
            int e = tid + rep * 256;
            int r = e >> 2, c4 = e & 3;
            float4 av = *(const float4*)&A[(size_t)(m0 + r) * K + k0 + c4 * 4];
            As[c4 * 4 + 0][r] = av.x;
            As[c4 * 4 + 1][r] = av.y;
            As[c4 * 4 + 2][r] = av.z;
            As[c4 * 4 + 3][r] = av.w;
        }
#pragma unroll
        for (int rep = 0; rep < 2; rep++) {
            int e = tid + rep * 256;
            int r = e >> 5, c4 = e & 31;
            float4 bv = *(const float4*)&Bmat[(size_t)(k0 + r) * N + n0 + c4 * 4];
            *(float4*)&Bs[r][c4 * 4] = bv;
        }
        __syncthreads();

#pragma unroll
        for (int kk = 0; kk < 16; kk++) {
            float a[8], b[8];
            *(float4*)&a[0] = *(const float4*)&As[kk][ty * 4];
            *(float4*)&a[4] = *(const float4*)&As[kk][64 + ty * 4];
            *(float4*)&b[0] = *(const float4*)&Bs[kk][tx * 4];
            *(float4*)&b[4] = *(const float4*)&Bs[kk][64 + tx * 4];
#pragma unroll
            for (int i = 0; i < 8; i++)
#pragma unroll
                for (int j = 0; j < 8; j++) acc[i][j] += a[i] * b[j];
        }
        __syncthreads();
    }

#pragma unroll
    for (int i = 0; i < 8; i++) {
        int m = m0 + ((i < 4) ? (ty * 4 + i) : (64 + ty * 4 + (i - 4)));
#pragma unroll
        for (int jg = 0; jg < 2; jg++) {
            int n = n0 + tx * 4 + jg * 64;
            float4 val;
            val.x = acc[i][jg * 4 + 0] + bias[n + 0];
            val.y = acc[i][jg * 4 + 1] + bias[n + 1];
            val.z = acc[i][jg * 4 + 2] + bias[n + 2];
            val.w = acc[i][jg * 4 + 3] + bias[n + 3];
            if (mode == 0) {
                *(float4*)&Cout[(size_t)m * N + n] = val;
            } else {
                int part = n >> 10;
                int rem = n & 1023;
                int h = rem >> 6;
                int d = rem & 63;
                int b = m >> 11;
                int t = m & 2047;
                float* dst = (part == 0) ? g_q : (part == 1) ? g_k : g_v;
                *(float4*)&dst[((((size_t)b * HH) + h) * TT + t) * DD + d] = val;
            }
        }
    }
}

// ---------------------------------------------------------------------------
// Two-pass causal attention with cached exponentials + precomputed regrow.
// 64 query rows per block, 64-key tiles, 256 threads, 4x4 micro-tile each:
//   ty = tid>>4 (row group of 4), tx = tid&15 (col group of 4).
// Pass 1: QK 4x4 micro-tiled, online max/sum (16-lane shuffle reduce),
//         cache e = exp(s - m_running) to gmem, running max per tile in smem.
// Pass 2: p = e * exp(m_it - m_final)/l, keep = p>0.01 || maskbit,
//         AV 4x4 micro-tiled with ts unrolled by 4.
// Dynamic smem: q[64][68] + kv[64][68] + a[64][68] + mh[64][32] = 60416 B.
// ---------------------------------------------------------------------------
__global__ void __launch_bounds__(256)
attn_kernel() {
    extern __shared__ float smem[];
    float (*q_sm)[68]  = (float(*)[68])(smem);
    float (*kv_sm)[68] = (float(*)[68])(smem + 64 * 68);
    float (*a_sm)[68]  = (float(*)[68])(smem + 2 * 64 * 68);
    float (*mh)[32]    = (float(*)[32])(smem + 3 * 64 * 68);

    const int bh = blockIdx.z * HH + blockIdx.y;
    const int qb = (int)(gridDim.x - 1 - blockIdx.x);  // heavy blocks first
    const int t0 = qb * 64;
    const int tid = threadIdx.x;
    const int ty = tid >> 4;
    const int tx = tid & 15;

    const float* qbase = g_q + ((size_t)bh * TT) * DD;
    const float* kbase = g_k + ((size_t)bh * TT) * DD;
    const float* vbase = g_v + ((size_t)bh * TT) * DD;

    // Load Q tile: 64 rows x 16 float4 = 1024 float4, 4 per thread
#pragma unroll
    for (int rep = 0; rep < 4; rep++) {
        int e = tid + rep * 256;
        int rr = e >> 4, c4 = e & 15;
        *(float4*)&q_sm[rr][c4 * 4] =
            *(const float4*)&qbase[(size_t)(t0 + rr) * DD + c4 * 4];
    }

    const int ntiles = qb + 1;
    float m[4], l[4];
#pragma unroll
    for (int i = 0; i < 4; i++) { m[i] = -1e30f; l[i] = 0.f; }

    // ---------------- Pass 1: QK, online max/sum, cache e ----------------
    for (int it = 0; it < ntiles; it++) {
        const int s0 = it * 64;
        __syncthreads();
#pragma unroll
        for (int rep = 0; rep < 4; rep++) {
            int e = tid + rep * 256;
            int rr = e >> 4, c4 = e & 15;
            *(float4*)&kv_sm[rr][c4 * 4] =
                *(const float4*)&kbase[(size_t)(s0 + rr) * DD + c4 * 4];
        }
        __syncthreads();

        float sc[4][4];
#pragma unroll
        for (int i = 0; i < 4; i++)
#pragma unroll
            for (int j = 0; j < 4; j++) sc[i][j] = 0.f;

#pragma unroll
        for (int d4 = 0; d4 < 16; d4++) {
            float4 qv[4], kv[4];
#pragma unroll
            for (int i = 0; i < 4; i++)
                qv[i] = *(const float4*)&q_sm[ty * 4 + i][d4 * 4];
#pragma unroll
            for (int j = 0; j < 4; j++)
                kv[j] = *(const float4*)&kv_sm[tx * 4 + j][d4 * 4];
#pragma unroll
            for (int i = 0; i < 4; i++)
#pragma unroll
                for (int j = 0; j < 4; j++)
                    sc[i][j] += qv[i].x * kv[j].x + qv[i].y * kv[j].y +
                                qv[i].z * kv[j].z + qv[i].w * kv[j].w;
        }

#pragma unroll
        for (int i = 0; i < 4; i++) {
            const int t = t0 + ty * 4 + i;
#pragma unroll
            for (int j = 0; j < 4; j++) {
                int s = s0 + tx * 4 + j;
                sc[i][j] = (s <= t) ? sc[i][j] * 0.125f : -1e30f;
            }
            float tm = fmaxf(fmaxf(sc[i][0], sc[i][1]),
                             fmaxf(sc[i][2], sc[i][3]));
#pragma unroll
            for (int off = 1; off < 16; off <<= 1)
                tm = fmaxf(tm, __shfl_xor_sync(0xffffffffu, tm, off));
            float mn = fmaxf(m[i], tm);
            float ev[4], ls = 0.f;
#pragma unroll
            for (int j = 0; j < 4; j++) {
                ev[j] = __expf(sc[i][j] - mn);
                ls += ev[j];
            }
#pragma unroll
            for (int off = 1; off < 16; off <<= 1)
                ls += __shfl_xor_sync(0xffffffffu, ls, off);
            l[i] = l[i] * __expf(m[i] - mn) + ls;
            m[i] = mn;
            if (tx == 0) mh[ty * 4 + i][it] = mn;
            float* erow = g_e + ((size_t)(bh * TT + t)) * TT;
            *(float4*)&erow[s0 + tx * 4] =
                make_float4(ev[0], ev[1], ev[2], ev[3]);
        }
    }

    // Per-tile rescale factors c_it = exp(m_it - m_final) / l
    __syncthreads();
#pragma unroll
    for (int i = 0; i < 4; i++) {
        const float inv_l = 1.0f / l[i];
        for (int it = tx; it < ntiles; it += 16)
            mh[ty * 4 + i][it] = __expf(mh[ty * 4 + i][it] - m[i]) * inv_l;
    }

    float oacc[4][4];
#pragma unroll
    for (int i = 0; i < 4; i++)
#pragma unroll
        for (int j = 0; j < 4; j++) oacc[i][j] = 0.f;

    // ---------------- Pass 2: sparsify cached e, A @ V ----------------
    for (int it = 0; it < ntiles; it++) {
        const int s0 = it * 64;
        __syncthreads();
#pragma unroll
        for (int rep = 0; rep < 4; rep++) {
            int e = tid + rep * 256;
            int rr = e >> 4, c4 = e & 15;
            *(float4*)&kv_sm[rr][c4 * 4] =
                *(const float4*)&vbase[(size_t)(s0 + rr) * DD + c4 * 4];
        }
#pragma unroll
        for (int i = 0; i < 4; i++) {
            const int row = ty * 4 + i;
            const int t = t0 + row;
            const float fac = mh[row][it];
            const float* erow = g_e + ((size_t)(bh * TT + t)) * TT;
            float4 ev = *(const float4*)&erow[s0 + tx * 4];
            uint32_t word = g_mask[((size_t)(bh * TT + t)) * (TT / 32) +
                                   (s0 >> 5) + (tx >> 3)];
            float a0 = ev.x * fac, a1 = ev.y * fac,
                  a2 = ev.z * fac, a3 = ev.w * fac;
            int bp = (tx & 7) * 4;
            a0 = (a0 > 0.01f || ((word >> (bp + 0)) & 1u)) ? a0 : 0.f;
            a1 = (a1 > 0.01f || ((word >> (bp + 1)) & 1u)) ? a1 : 0.f;
            a2 = (a2 > 0.01f || ((word >> (bp + 2)) & 1u)) ? a2 : 0.f;
            a3 = (a3 > 0.01f || ((word >> (bp + 3)) & 1u)) ? a3 : 0.f;
            *(float4*)&a_sm[row][tx * 4] = make_float4(a0, a1, a2, a3);
        }
        __syncthreads();

#pragma unroll
        for (int g = 0; g < 16; g++) {
            float4 a4[4], v4[4];
#pragma unroll
            for (int i = 0; i < 4; i++)
                a4[i] = *(const float4*)&a_sm[ty * 4 + i][g * 4];
#pragma unroll
            for (int k = 0; k < 4; k++)
                v4[k] = *(const float4*)&kv_sm[g * 4 + k][tx * 4];
#pragma unroll
            for (int i = 0; i < 4; i++) {
                oacc[i][0] += a4[i].x * v4[0].x + a4[i].y * v4[1].x +
                              a4[i].z * v4[2].x + a4[i].w * v4[3].x;
                oacc[i][1] += a4[i].x * v4[0].y + a4[i].y * v4[1].y +
                              a4[i].z * v4[2].y + a4[i].w * v4[3].y;
                oacc[i][2] += a4[i].x * v4[0].z + a4[i].y * v4[1].z +
                              a4[i].z * v4[2].z + a4[i].w * v4[3].z;
                oacc[i][3] += a4[i].x * v4[0].w + a4[i].y * v4[1].w +
                              a4[i].z * v4[2].w + a4[i].w * v4[3].w;
            }
        }
    }

    // Store to [B, T, C] with c = h*64 + d, d = tx*4..tx*4+3
    const int b = blockIdx.z, h = blockIdx.y;
#pragma unroll
    for (int i = 0; i < 4; i++) {
        const int t = t0 + ty * 4 + i;
        float* dst = g_ao + ((size_t)(b * TT + t) * CC) + h * 64 + tx * 4;
        *(float4*)dst = make_float4(oacc[i][0], oacc[i][1],
                                    oacc[i][2], oacc[i][3]);
    }
}

// ---------------------------------------------------------------------------
extern "C" void kernel_launch(void* const* d_in, const int* in_sizes, int n_in,
                              void* d_out, int out_size) {
    const float* x    = (const float*)d_in[0];
    const float* Wqkv = (const float*)d_in[1];
    const float* bqkv = (const float*)d_in[2];
    const float* Wout = (const float*)d_in[3];
    const float* bout = (const float*)d_in[4];
    float* out = (float*)d_out;

    const int ATTN_SMEM = (3 * 64 * 68 + 64 * 32) * 4;  // 60416 B
    cudaFuncSetAttribute(attn_kernel,
                         cudaFuncAttributeMaxDynamicSharedMemorySize,
                         ATTN_SMEM);

    // 0) Regrow bitmask (input-independent)
    mask_kernel<<<dim3(8, TT, BB * HH), 256>>>();

    // 1) QKV projection, scattered to [B,H,T,D]
    gemm_kernel<<<dim3(3 * CC / 128, BB * TT / 128), 256>>>(
        x, Wqkv, bqkv, nullptr, BB * TT, 3 * CC, CC, 1);

    // 2) Causal attention + neuroplastic sparsification
    attn_kernel<<<dim3(TT / 64, HH, BB), 256, ATTN_SMEM>>>();

    // 3) Output projection
    gemm_kernel<<<dim3(CC / 128, BB * TT / 128), 256>>>(
        nullptr, Wout, bout, out, BB * TT, CC, CC, 0);
}